// round 4
// baseline (speedup 1.0000x reference)
#include <cuda_runtime.h>
#include <cstdint>
#include <cstddef>

// ---------------- problem constants ----------------
#define D_MODEL   1024
#define D_PROJ    256
#define MTILE     64                   // rows per CTA
#define KCHUNK    32                   // fp32 per K chunk = 128B per row
#define NCHUNKS   (D_MODEL / KCHUNK)   // 32
#define EPS1      1e-5f

// smem map (bytes):
//   [0, 4096)      suv: u[256] v[256] g2[256] b2[256]
//   [4096, 4608)   s1p[64], s2p[64]
//   [4608, 5120)   ca[64], cb[64]
//   [8192, ...)    2 pipeline stages: A 8KB + B 32KB each
//   epilogue reuses stage0: rowacc[64][4][2], mu2[64], rs2[64]
#define SMEM_STAGE_OFF 8192
#define A_BYTES   (MTILE * KCHUNK * 4)     // 8192
#define B_BYTES   (D_PROJ * KCHUNK * 4)    // 32768
#define STAGE_BYTES (A_BYTES + B_BYTES)    // 40960
#define SMEM_BYTES (SMEM_STAGE_OFF + 2 * STAGE_BYTES)   // 90112

// ---------------- device scratch ----------------
// g_Wp layout: [p][(d>>4)*16 + s] with s = 4*(kk&3)+(kk>>2), kk = d&15:
// each 16B group q of a 64B half holds kk = {q, q+4, q+8, q+12}.
__device__ float g_Wp[D_PROJ * D_MODEL];
__device__ float g_u[D_PROJ];
__device__ float g_v[D_PROJ];

// ---------------- helpers ----------------
static __device__ __forceinline__ uint32_t smem_u32(const void* p) {
    uint32_t a;
    asm("{ .reg .u64 t; cvta.to.shared.u64 t, %1; cvt.u32.u64 %0, t; }" : "=r"(a) : "l"(p));
    return a;
}

static __device__ __forceinline__ uint32_t swz(int r) {   // 16B-group xor swizzle
    return (uint32_t)((r + (r >> 2)) & 3);
}

#define CP_COMMIT() asm volatile("cp.async.commit_group;" ::: "memory")

static __device__ __forceinline__ uint32_t f2tf32(float f) {
    uint32_t u;
    asm("cvt.rna.tf32.f32 %0, %1;" : "=r"(u) : "f"(f));
    return u;
}

#define MMA_TF32(d, a0, a1, a2, a3, b0, b1)                                   \
    asm volatile("mma.sync.aligned.m16n8k8.row.col.f32.tf32.tf32.f32 "        \
        "{%0,%1,%2,%3}, {%4,%5,%6,%7}, {%8,%9}, {%0,%1,%2,%3};"               \
        : "+f"((d)[0]), "+f"((d)[1]), "+f"((d)[2]), "+f"((d)[3])              \
        : "r"(a0), "r"(a1), "r"(a2), "r"(a3), "r"(b0), "r"(b1))

#define LDS128F(v, addr)                                                      \
    asm volatile("ld.shared.v4.f32 {%0,%1,%2,%3}, [%4];"                      \
        : "=f"((v).x), "=f"((v).y), "=f"((v).z), "=f"((v).w) : "r"(addr))

#define LDS64U(r0, r1, addr)                                                  \
    asm volatile("ld.shared.v2.b32 {%0,%1}, [%2];"                            \
        : "=r"(r0), "=r"(r1) : "r"(addr))

// ---------------- prep: W' = g1.*W (tf32-rna), permuted layout; u, v ----------------
__global__ void __launch_bounds__(256) prep_kernel(
    const float* __restrict__ W, const float* __restrict__ g1,
    const float* __restrict__ b1, const float* __restrict__ bias)
{
    __shared__ float ru[8], rv[8];
    int p = blockIdx.x, t = threadIdx.x;
    const float* wrow = W + (size_t)p * D_MODEL;
    float u = 0.f, v = 0.f;
#pragma unroll
    for (int i = 0; i < 4; ++i) {
        int d = t + i * 256;
        float w  = wrow[d];
        float gw = g1[d] * w;
        u += gw;
        v += b1[d] * w;
        int kc = d >> 4, kk = d & 15;
        int s = ((kk & 3) << 2) | (kk >> 2);
        g_Wp[(size_t)p * D_MODEL + kc * 16 + s] = __uint_as_float(f2tf32(gw));
    }
#pragma unroll
    for (int o = 16; o > 0; o >>= 1) {
        u += __shfl_xor_sync(0xFFFFFFFFu, u, o);
        v += __shfl_xor_sync(0xFFFFFFFFu, v, o);
    }
    if ((t & 31) == 0) { ru[t >> 5] = u; rv[t >> 5] = v; }
    __syncthreads();
    if (t == 0) {
        float uu = 0.f, vv = 0.f;
#pragma unroll
        for (int i = 0; i < 8; ++i) { uu += ru[i]; vv += rv[i]; }
        g_u[p] = uu;
        g_v[p] = vv + bias[p];
    }
}

// ---------------- main fused kernel ----------------
__global__ void __launch_bounds__(256, 2) fused_kernel(
    const float* __restrict__ x,
    const float* __restrict__ g2v, const float* __restrict__ b2v,
    float* __restrict__ out)
{
    extern __shared__ char smem[];
    const uint32_t sb = smem_u32(smem);
    const int tid  = threadIdx.x;
    const int lane = tid & 31;
    const int wid  = tid >> 5;
    const int wm   = wid >> 2;          // 0..1
    const int wn   = wid & 3;           // 0..3
    const int qt   = lane & 3;
    const int qr   = lane >> 2;

    float* suv = (float*)smem;          // u, v, g2, b2
    suv[tid]       = g_u[tid];
    suv[256 + tid] = g_v[tid];
    suv[512 + tid] = g2v[tid];
    suv[768 + tid] = b2v[tid];

    const size_t row0 = (size_t)blockIdx.x * MTILE;

    // ---- loader thread-constant addressing ----
    // A: thread -> row ar = tid>>2, slot-byte jj = tid&3, m=0..3, h=0..1.
    const int ar = tid >> 2;
    const int jj = tid & 3;
    const uint32_t asw = swz(ar);
    const char* a_src0 = (const char*)(x + row0 * D_MODEL) + (size_t)ar * 4096 + (size_t)jj * 16;
    const uint32_t a_dst0 = sb + SMEM_STAGE_OFF + (uint32_t)ar * 128 + (uint32_t)jj * 4;
    // B: thread -> rows p = i*32 + tp (i=0..7), group gq = tid&7 (h = gq>>2, q = gq&3).
    const int tp = tid >> 3;
    const int gq = tid & 7;
    const int bh = gq >> 2;
    const int bq = gq & 3;
    const uint32_t bsw = swz(tp);       // swz(i*32+tp) == swz(tp), since 40*i ≡ 0 (mod 4)
    const char* b_src0 = (const char*)g_Wp + (size_t)tp * 4096 + (size_t)bh * 64 + (size_t)bq * 16;
    const uint32_t b_dst0 = sb + SMEM_STAGE_OFF + A_BYTES + (uint32_t)tp * 128
                          + (uint32_t)bh * 64 + (((uint32_t)bq ^ bsw) << 4);

#define LOAD_CHUNK(KC, SOFF)                                                   \
    do {                                                                       \
        const char* _as = a_src0 + (size_t)(KC) * 128;                         \
        _Pragma("unroll")                                                      \
        for (int h = 0; h < 2; ++h)                                            \
            _Pragma("unroll")                                                  \
            for (int m = 0; m < 4; ++m)                                        \
                asm volatile("cp.async.ca.shared.global [%0], [%1], 4;"        \
                    :: "r"(a_dst0 + (SOFF) + (uint32_t)h * 64                  \
                           + ((((uint32_t)m) ^ asw) << 4)),                    \
                       "l"(_as + h * 64 + m * 4));                             \
        const char* _bs = b_src0 + (size_t)(KC) * 128;                         \
        _Pragma("unroll")                                                      \
        for (int i = 0; i < 8; ++i)                                            \
            asm volatile("cp.async.cg.shared.global [%0], [%1], 16;"           \
                :: "r"(b_dst0 + (SOFF) + (uint32_t)i * 4096),                  \
                   "l"(_bs + (size_t)i * 131072));                             \
    } while (0)

    // ---- fragment addresses (stage 0, half 0), hoisted once ----
    uint32_t aAd[2][2];
#pragma unroll
    for (int mt = 0; mt < 2; ++mt) {
        int r0 = wm * 32 + mt * 16 + qr;
        int r8 = r0 + 8;
        aAd[mt][0] = sb + SMEM_STAGE_OFF + (uint32_t)r0 * 128 + ((((uint32_t)qt) ^ swz(r0)) << 4);
        aAd[mt][1] = sb + SMEM_STAGE_OFF + (uint32_t)r8 * 128 + ((((uint32_t)qt) ^ swz(r8)) << 4);
    }
    uint32_t bAd[8];
#pragma unroll
    for (int nt = 0; nt < 8; ++nt) {
        int p = wn * 64 + nt * 8 + qr;
        bAd[nt] = sb + SMEM_STAGE_OFF + A_BYTES + (uint32_t)p * 128
                + ((((uint32_t)qt) ^ swz(p)) << 4);
    }

    float acc[2][8][4];
#pragma unroll
    for (int a = 0; a < 2; ++a)
#pragma unroll
        for (int b = 0; b < 8; ++b)
#pragma unroll
            for (int c = 0; c < 4; ++c) acc[a][b][c] = 0.f;

    float s1r[4] = {0.f, 0.f, 0.f, 0.f};
    float s2r[4] = {0.f, 0.f, 0.f, 0.f};
    const bool do_stats = (wn == 0);

#define COMPUTE_CHUNK(SOFF)                                                    \
    do {                                                                       \
        _Pragma("unroll")                                                      \
        for (int h = 0; h < 2; ++h) {                                          \
            const uint32_t hoff = (SOFF) + (uint32_t)h * 64;                   \
            uint32_t au[2][8];                                                 \
            _Pragma("unroll")                                                  \
            for (int mt = 0; mt < 2; ++mt) {                                   \
                float4 alo, ahi;                                               \
                LDS128F(alo, aAd[mt][0] + hoff);                               \
                LDS128F(ahi, aAd[mt][1] + hoff);                               \
                if (do_stats) {                                                \
                    s1r[mt * 2]     += (alo.x + alo.y) + (alo.z + alo.w);      \
                    s2r[mt * 2]     += (alo.x * alo.x + alo.y * alo.y)         \
                                     + (alo.z * alo.z + alo.w * alo.w);        \
                    s1r[mt * 2 + 1] += (ahi.x + ahi.y) + (ahi.z + ahi.w);      \
                    s2r[mt * 2 + 1] += (ahi.x * ahi.x + ahi.y * ahi.y)         \
                                     + (ahi.z * ahi.z + ahi.w * ahi.w);        \
                }                                                              \
                au[mt][0] = f2tf32(alo.x); au[mt][1] = f2tf32(ahi.x);          \
                au[mt][2] = f2tf32(alo.y); au[mt][3] = f2tf32(ahi.y);          \
                au[mt][4] = f2tf32(alo.z); au[mt][5] = f2tf32(ahi.z);          \
                au[mt][6] = f2tf32(alo.w); au[mt][7] = f2tf32(ahi.w);          \
            }                                                                  \
            _Pragma("unroll")                                                  \
            for (int s = 0; s < 2; ++s) {                                      \
                uint32_t b0[8], b1[8];                                         \
                _Pragma("unroll")                                              \
                for (int nt = 0; nt < 8; ++nt)                                 \
                    LDS64U(b0[nt], b1[nt], bAd[nt] + hoff + (uint32_t)s * 8);  \
                _Pragma("unroll")                                              \
                for (int mt = 0; mt < 2; ++mt)                                 \
                    _Pragma("unroll")                                          \
                    for (int nt = 0; nt < 8; ++nt)                             \
                        MMA_TF32(acc[mt][nt], au[mt][4 * s], au[mt][4 * s + 1],\
                                 au[mt][4 * s + 2], au[mt][4 * s + 3],         \
                                 b0[nt], b1[nt]);                              \
            }                                                                  \
        }                                                                      \
    } while (0)

    // ---------------- mainloop: 2-stage ping-pong, unrolled x2 ----------------
    LOAD_CHUNK(0, 0u); CP_COMMIT();

#pragma unroll 1
    for (int kc = 0; kc < NCHUNKS; kc += 2) {
        // even chunk: compute stage 0, load kc+1 -> stage 1
        asm volatile("cp.async.wait_group 0;" ::: "memory");
        __syncthreads();
        LOAD_CHUNK(kc + 1, (uint32_t)STAGE_BYTES); CP_COMMIT();
        COMPUTE_CHUNK(0u);

        // odd chunk: compute stage 1, load kc+2 -> stage 0
        asm volatile("cp.async.wait_group 0;" ::: "memory");
        __syncthreads();
        if (kc + 2 < NCHUNKS) { LOAD_CHUNK(kc + 2, 0u); }
        CP_COMMIT();
        COMPUTE_CHUNK((uint32_t)STAGE_BYTES);
    }

    // ---------------- LN1 finalize ----------------
    float* s1p = (float*)(smem + 4096);         // [64]
    float* s2p = s1p + 64;                      // [64]
    float* ca  = (float*)(smem + 4608);         // [64]
    float* cb  = ca + 64;                       // [64]
    float* rowacc = (float*)(smem + SMEM_STAGE_OFF);        // [64][4][2]
    float* mu2a = rowacc + 512;                 // [64]
    float* rs2a = mu2a + 64;                    // [64]

    __syncthreads();
    if (wn == 0) {
#pragma unroll
        for (int sl = 0; sl < 4; ++sl) {
            float a = s1r[sl], b = s2r[sl];
            a += __shfl_xor_sync(0xFFFFFFFFu, a, 1);
            b += __shfl_xor_sync(0xFFFFFFFFu, b, 1);
            a += __shfl_xor_sync(0xFFFFFFFFu, a, 2);
            b += __shfl_xor_sync(0xFFFFFFFFu, b, 2);
            if (qt == 0) {
                int rr = wm * 32 + (sl >> 1) * 16 + qr + 8 * (sl & 1);
                s1p[rr] = a;
                s2p[rr] = b;
            }
        }
    }
    rowacc[tid] = 0.f; rowacc[tid + 256] = 0.f;
    __syncthreads();

    if (tid < 64) {
        float mu  = s1p[tid] * (1.0f / (float)D_MODEL);
        float var = fmaf(-mu, mu, s2p[tid] * (1.0f / (float)D_MODEL));
        float rs  = rsqrtf(var + EPS1);
        ca[tid] = rs;
        cb[tid] = -mu * rs;
    }
    __syncthreads();

    // ---------------- h = ca*acc + cb*u + v; LN2 partial sums ----------------
#pragma unroll
    for (int mt = 0; mt < 2; ++mt) {
#pragma unroll
        for (int b = 0; b < 2; ++b) {
            int rr = wm * 32 + mt * 16 + qr + 8 * b;
            float cav = ca[rr], cbv = cb[rr];
            float t1 = 0.f, t2 = 0.f;
#pragma unroll
            for (int nt = 0; nt < 8; ++nt) {
                int p0 = wn * 64 + nt * 8 + 2 * qt;
                float h0 = fmaf(cav, acc[mt][nt][2 * b],     fmaf(cbv, suv[p0],     suv[256 + p0]));
                float h1 = fmaf(cav, acc[mt][nt][2 * b + 1], fmaf(cbv, suv[p0 + 1], suv[256 + p0 + 1]));
                acc[mt][nt][2 * b]     = h0;
                acc[mt][nt][2 * b + 1] = h1;
                t1 += h0 + h1;
                t2 += h0 * h0 + h1 * h1;
            }
            t1 += __shfl_xor_sync(0xFFFFFFFFu, t1, 1);
            t2 += __shfl_xor_sync(0xFFFFFFFFu, t2, 1);
            t1 += __shfl_xor_sync(0xFFFFFFFFu, t1, 2);
            t2 += __shfl_xor_sync(0xFFFFFFFFu, t2, 2);
            if (qt == 0) {
                rowacc[(rr * 4 + wn) * 2]     = t1;
                rowacc[(rr * 4 + wn) * 2 + 1] = t2;
            }
        }
    }
    __syncthreads();

    if (tid < 64) {
        float t1 = 0.f, t2 = 0.f;
#pragma unroll
        for (int w = 0; w < 4; ++w) {
            t1 += rowacc[(tid * 4 + w) * 2];
            t2 += rowacc[(tid * 4 + w) * 2 + 1];
        }
        float mu  = t1 * (1.0f / (float)D_PROJ);
        float var = fmaf(-mu, mu, t2 * (1.0f / (float)D_PROJ));
        mu2a[tid] = mu;
        rs2a[tid] = rsqrtf(var + EPS1);
    }
    __syncthreads();

    // ---------------- normalize + store ----------------
    float* outp = out + row0 * D_PROJ;
#pragma unroll
    for (int mt = 0; mt < 2; ++mt) {
#pragma unroll
        for (int b = 0; b < 2; ++b) {
            int rr = wm * 32 + mt * 16 + qr + 8 * b;
            float mu = mu2a[rr], rs = rs2a[rr];
#pragma unroll
            for (int nt = 0; nt < 8; ++nt) {
                int p0 = wn * 64 + nt * 8 + 2 * qt;
                float o0 = fmaf((acc[mt][nt][2 * b]     - mu) * rs, suv[512 + p0],     suv[768 + p0]);
                float o1 = fmaf((acc[mt][nt][2 * b + 1] - mu) * rs, suv[512 + p0 + 1], suv[768 + p0 + 1]);
                float2 o = make_float2(o0, o1);
                *(float2*)(outp + (size_t)rr * D_PROJ + p0) = o;
            }
        }
    }
#undef LOAD_CHUNK
#undef COMPUTE_CHUNK
}

// ---------------- launch ----------------
extern "C" void kernel_launch(void* const* d_in, const int* in_sizes, int n_in,
                              void* d_out, int out_size)
{
    const float* x    = (const float*)d_in[0];
    const float* g1   = (const float*)d_in[1];
    const float* b1   = (const float*)d_in[2];
    const float* W    = (const float*)d_in[3];
    const float* bias = (const float*)d_in[4];
    const float* g2   = (const float*)d_in[5];
    const float* b2   = (const float*)d_in[6];
    float* out = (float*)d_out;

    int n_tok = in_sizes[0] / D_MODEL;          // 65536
    int grid  = n_tok / MTILE;                  // 1024

    prep_kernel<<<D_PROJ, 256>>>(W, g1, b1, bias);

    cudaFuncSetAttribute(fused_kernel, cudaFuncAttributeMaxDynamicSharedMemorySize, SMEM_BYTES);
    fused_kernel<<<grid, 256, SMEM_BYTES>>>(x, g2, b2, out);
}

// round 5
// speedup vs baseline: 1.0771x; 1.0771x over previous
#include <cuda_runtime.h>
#include <cstdint>
#include <cstddef>

// ---------------- problem constants ----------------
#define D_MODEL   1024
#define D_PROJ    256
#define MTILE     64
#define NCHUNKS   32                   // K chunks of 32 fp32 (128B per row)
#define EPS1      1e-5f

// ---------------- smem map (bytes) ----------------
#define SUV_OFF   0                    // u[256] v[256] g2[256] b2[256] = 4KB
#define S1P_OFF   4096                 // 128 floats
#define S2P_OFF   4608                 // 128 floats
#define CA_OFF    5120                 // 64 floats
#define CB_OFF    5376                 // 64 floats
#define A0_OFF    8192                 // A stage 0: 64 rows x 128B = 8KB (tf32, permuted)
#define A1_OFF    16384                // A stage 1
#define B0_OFF    24576                // B stage 0: 256 rows x 128B = 32KB
#define B1_OFF    57344                // B stage 1
#define SMEM_BYTES 90112               // 88KB -> 2 CTAs/SM
// epilogue scratch reuses A-stage region
#define ROWACC_OFF 8192                // [64][4][2] floats = 2KB
#define MU2_OFF    10240               // 64 floats
#define RS2_OFF    10496               // 64 floats

// ---------------- device scratch ----------------
// g_Wp layout: [p][(d>>4)*16 + s], s = 4*(kk&3)+(kk>>2), kk = d&15.
__device__ float g_Wp[D_PROJ * D_MODEL];
__device__ float g_u[D_PROJ];
__device__ float g_v[D_PROJ];

// ---------------- helpers ----------------
static __device__ __forceinline__ uint32_t smem_u32(const void* p) {
    uint32_t a;
    asm("{ .reg .u64 t; cvta.to.shared.u64 t, %1; cvt.u32.u64 %0, t; }" : "=r"(a) : "l"(p));
    return a;
}

static __device__ __forceinline__ uint32_t f2tf32(float f) {
    uint32_t u;
    asm("cvt.rna.tf32.f32 %0, %1;" : "=r"(u) : "f"(f));
    return u;
}

// sigma(r) = ((r&1)<<2) | ((r>>1)&3), premultiplied by 16
static __device__ __forceinline__ uint32_t sig16(int r) {
    return ((((uint32_t)r & 1u) << 2) | (((uint32_t)r >> 1) & 3u)) << 4;
}

#define CP_COMMIT() asm volatile("cp.async.commit_group;" ::: "memory")
#define CP_WAIT0()  asm volatile("cp.async.wait_group 0;" ::: "memory")

#define CP16(saddr, gptr) \
    asm volatile("cp.async.cg.shared.global [%0], [%1], 16;" :: "r"(saddr), "l"(gptr))

#define STS128(addr, c0, c1, c2, c3)                                          \
    asm volatile("st.shared.v4.b32 [%0], {%1,%2,%3,%4};"                      \
        :: "r"(addr), "r"(c0), "r"(c1), "r"(c2), "r"(c3))

#define LDS128U(v, addr)                                                      \
    asm volatile("ld.shared.v4.b32 {%0,%1,%2,%3}, [%4];"                      \
        : "=r"((v).x), "=r"((v).y), "=r"((v).z), "=r"((v).w) : "r"(addr))

#define MMA_TF32(d, a0, a1, a2, a3, b0, b1)                                   \
    asm volatile("mma.sync.aligned.m16n8k8.row.col.f32.tf32.tf32.f32 "        \
        "{%0,%1,%2,%3}, {%4,%5,%6,%7}, {%8,%9}, {%0,%1,%2,%3};"               \
        : "+f"((d)[0]), "+f"((d)[1]), "+f"((d)[2]), "+f"((d)[3])              \
        : "r"(a0), "r"(a1), "r"(a2), "r"(a3), "r"(b0), "r"(b1))

// ---------------- prep: W' = g1.*W (tf32-rna), permuted layout; u, v ----------------
__global__ void __launch_bounds__(256) prep_kernel(
    const float* __restrict__ W, const float* __restrict__ g1,
    const float* __restrict__ b1, const float* __restrict__ bias)
{
    __shared__ float ru[8], rv[8];
    int p = blockIdx.x, t = threadIdx.x;
    const float* wrow = W + (size_t)p * D_MODEL;
    float u = 0.f, v = 0.f;
#pragma unroll
    for (int i = 0; i < 4; ++i) {
        int d = t + i * 256;
        float w  = wrow[d];
        float gw = g1[d] * w;
        u += gw;
        v += b1[d] * w;
        int kc = d >> 4, kk = d & 15;
        int s = ((kk & 3) << 2) | (kk >> 2);
        g_Wp[(size_t)p * D_MODEL + kc * 16 + s] = __uint_as_float(f2tf32(gw));
    }
#pragma unroll
    for (int o = 16; o > 0; o >>= 1) {
        u += __shfl_xor_sync(0xFFFFFFFFu, u, o);
        v += __shfl_xor_sync(0xFFFFFFFFu, v, o);
    }
    if ((t & 31) == 0) { ru[t >> 5] = u; rv[t >> 5] = v; }
    __syncthreads();
    if (t == 0) {
        float uu = 0.f, vv = 0.f;
#pragma unroll
        for (int i = 0; i < 8; ++i) { uu += ru[i]; vv += rv[i]; }
        g_u[p] = uu;
        g_v[p] = vv + bias[p];
    }
}

// ---------------- main fused kernel ----------------
__global__ void __launch_bounds__(128, 2) fused_kernel(
    const float* __restrict__ x,
    const float* __restrict__ g2v, const float* __restrict__ b2v,
    float* __restrict__ out)
{
    extern __shared__ char smem[];
    const uint32_t sb = smem_u32(smem);
    const int tid  = threadIdx.x;
    const int lane = tid & 31;
    const int wn   = tid >> 5;          // warp 0..3 -> n-slice
    const int qt   = lane & 3;
    const int qr   = lane >> 2;

    float* suv = (float*)smem;          // u, v, g2, b2
    suv[tid]        = g_u[tid];
    suv[tid + 128]  = g_u[tid + 128];
    suv[256 + tid]        = g_v[tid];
    suv[256 + tid + 128]  = g_v[tid + 128];
    suv[512 + tid]        = g2v[tid];
    suv[512 + tid + 128]  = g2v[tid + 128];
    suv[768 + tid]        = b2v[tid];
    suv[768 + tid + 128]  = b2v[tid + 128];

    const size_t row0 = (size_t)blockIdx.x * MTILE;

    // ---- A loader constants: thread -> (row lr, half lh) ----
    const int lr = tid & 63;
    const int lh = tid >> 6;
    const uint32_t asw16 = sig16(lr);
    const uint32_t ah64  = (uint32_t)lh << 6;          // (4h)<<4
    const char* a_src = (const char*)x + (row0 + lr) * 4096 + (size_t)lh * 64;
    const uint32_t a_dst = sb + A0_OFF + (uint32_t)lr * 128;

    // ---- B loader constants: thread -> rows tid and tid+128 ----
    const uint32_t bsw16 = sig16(tid);
    const char* b_src = (const char*)g_Wp + (size_t)tid * 4096;
    const uint32_t b_dst = sb + B0_OFF + (uint32_t)tid * 128;

    // ---- fragment base addresses (stage 0); everything else is immediate ----
    const uint32_t fsw16 = sig16(qr);
    const uint32_t aF0 = sb + A0_OFF + (uint32_t)qr * 128 + ((((uint32_t)qt << 4)       ) ^ fsw16);
    const uint32_t aF1 = sb + A0_OFF + (uint32_t)qr * 128 + ((((uint32_t)qt << 4) | 64u) ^ fsw16);
    const uint32_t bF0 = sb + B0_OFF + (uint32_t)(wn * 64 + qr) * 128 + ((((uint32_t)qt << 4)       ) ^ fsw16);
    const uint32_t bF1 = sb + B0_OFF + (uint32_t)(wn * 64 + qr) * 128 + ((((uint32_t)qt << 4) | 64u) ^ fsw16);

    float acc[4][8][4];
#pragma unroll
    for (int a = 0; a < 4; ++a)
#pragma unroll
        for (int b = 0; b < 8; ++b)
#pragma unroll
            for (int c = 0; c < 4; ++c) acc[a][b][c] = 0.f;

    float s1 = 0.f, s2 = 0.f;           // exact LN1 partials for (row lr, half lh)
    float4 xr0, xr1, xr2, xr3;          // in-flight raw A half-row (16 floats)

#define LDA(KC)                                                                \
    do {                                                                       \
        const float4* _p = (const float4*)(a_src + (size_t)(KC) * 128);        \
        xr0 = _p[0]; xr1 = _p[1]; xr2 = _p[2]; xr3 = _p[3];                    \
    } while (0)

#define STATS()                                                                \
    do {                                                                       \
        s1 += ((xr0.x + xr0.y) + (xr0.z + xr0.w))                              \
            + ((xr1.x + xr1.y) + (xr1.z + xr1.w))                              \
            + ((xr2.x + xr2.y) + (xr2.z + xr2.w))                              \
            + ((xr3.x + xr3.y) + (xr3.z + xr3.w));                             \
        s2 += ((xr0.x * xr0.x + xr0.y * xr0.y) + (xr0.z * xr0.z + xr0.w * xr0.w)) \
            + ((xr1.x * xr1.x + xr1.y * xr1.y) + (xr1.z * xr1.z + xr1.w * xr1.w)) \
            + ((xr2.x * xr2.x + xr2.y * xr2.y) + (xr2.z * xr2.z + xr2.w * xr2.w)) \
            + ((xr3.x * xr3.x + xr3.y * xr3.y) + (xr3.z * xr3.z + xr3.w * xr3.w)); \
    } while (0)

#define STSA(SOFF)                                                             \
    do {                                                                       \
        STS128(a_dst + (SOFF) + ((ah64 |  0u) ^ asw16),                        \
               f2tf32(xr0.x), f2tf32(xr1.x), f2tf32(xr2.x), f2tf32(xr3.x));    \
        STS128(a_dst + (SOFF) + ((ah64 | 16u) ^ asw16),                        \
               f2tf32(xr0.y), f2tf32(xr1.y), f2tf32(xr2.y), f2tf32(xr3.y));    \
        STS128(a_dst + (SOFF) + ((ah64 | 32u) ^ asw16),                        \
               f2tf32(xr0.z), f2tf32(xr1.z), f2tf32(xr2.z), f2tf32(xr3.z));    \
        STS128(a_dst + (SOFF) + ((ah64 | 48u) ^ asw16),                        \
               f2tf32(xr0.w), f2tf32(xr1.w), f2tf32(xr2.w), f2tf32(xr3.w));    \
    } while (0)

#define CPB(KC, SOFF)                                                          \
    do {                                                                       \
        const char* _s = b_src + (size_t)(KC) * 128;                           \
        _Pragma("unroll")                                                      \
        for (int q = 0; q < 8; ++q) {                                          \
            CP16(b_dst + (SOFF) + (((uint32_t)q << 4) ^ bsw16), _s + q * 16);  \
            CP16(b_dst + (SOFF) + 16384u + (((uint32_t)q << 4) ^ bsw16),       \
                 _s + 524288 + q * 16);                                        \
        }                                                                      \
    } while (0)

#define COMPUTE(SA, SB)                                                        \
    do {                                                                       \
        _Pragma("unroll")                                                      \
        for (int h = 0; h < 2; ++h) {                                          \
            const uint32_t _af = (h ? aF1 : aF0) + (SA);                       \
            const uint32_t _bf = (h ? bF1 : bF0) + (SB);                       \
            uint4 bb[8];                                                       \
            _Pragma("unroll")                                                  \
            for (int nt = 0; nt < 8; ++nt)                                     \
                LDS128U(bb[nt], _bf + (uint32_t)nt * 1024);                    \
            _Pragma("unroll")                                                  \
            for (int mt = 0; mt < 4; ++mt) {                                   \
                uint4 alo, ahi;                                                \
                LDS128U(alo, _af + (uint32_t)mt * 2048);                       \
                LDS128U(ahi, _af + (uint32_t)mt * 2048 + 1024);                \
                _Pragma("unroll")                                              \
                for (int nt = 0; nt < 8; ++nt) {                               \
                    MMA_TF32(acc[mt][nt], alo.x, ahi.x, alo.y, ahi.y,          \
                             bb[nt].x, bb[nt].y);                              \
                    MMA_TF32(acc[mt][nt], alo.z, ahi.z, alo.w, ahi.w,          \
                             bb[nt].z, bb[nt].w);                              \
                }                                                              \
            }                                                                  \
        }                                                                      \
    } while (0)

    // ---------------- prologue ----------------
    LDA(0);
    STATS();
    STSA(0u);                           // chunk 0 -> A stage 0
    LDA(1);
    CPB(0, 0u); CP_COMMIT();            // chunk 0 -> B stage 0

#define ITER(KC, SA_CUR, SB_CUR, SA_NXT, SB_NXT)                               \
    do {                                                                       \
        CP_WAIT0();                                                            \
        __syncthreads();                                                       \
        const int _kn = ((KC) + 1 < NCHUNKS) ? (KC) + 1 : NCHUNKS - 1;         \
        CPB(_kn, SB_NXT); CP_COMMIT();                                         \
        if ((KC) < NCHUNKS - 1) STATS();                                       \
        STSA(SA_NXT);                                                          \
        const int _kn2 = ((KC) + 2 < NCHUNKS) ? (KC) + 2 : NCHUNKS - 1;        \
        LDA(_kn2);                                                             \
        COMPUTE(SA_CUR, SB_CUR);                                               \
    } while (0)

#pragma unroll 1
    for (int kc = 0; kc < NCHUNKS; kc += 2) {
        ITER(kc,     0u,    0u,    8192u, 32768u);
        ITER(kc + 1, 8192u, 32768u, 0u,   0u);
    }

    // ---------------- LN1 finalize (exact, zero redundancy) ----------------
    float* s1p = (float*)(smem + S1P_OFF);
    float* s2p = (float*)(smem + S2P_OFF);
    float* ca  = (float*)(smem + CA_OFF);
    float* cb  = (float*)(smem + CB_OFF);
    float* rowacc = (float*)(smem + ROWACC_OFF);   // [64][4][2]
    float* mu2a = (float*)(smem + MU2_OFF);
    float* rs2a = (float*)(smem + RS2_OFF);

    s1p[tid] = s1;
    s2p[tid] = s2;
    rowacc[tid] = 0.f; rowacc[tid + 128] = 0.f;
    rowacc[tid + 256] = 0.f; rowacc[tid + 384] = 0.f;
    __syncthreads();

    if (tid < 64) {
        float a = s1p[tid] + s1p[tid + 64];
        float b = s2p[tid] + s2p[tid + 64];
        float mu  = a * (1.0f / (float)D_MODEL);
        float var = fmaf(-mu, mu, b * (1.0f / (float)D_MODEL));
        float rs  = rsqrtf(var + EPS1);
        ca[tid] = rs;
        cb[tid] = -mu * rs;
    }
    __syncthreads();

    // ---------------- h = ca*acc + cb*u + v; LN2 partial sums ----------------
#pragma unroll
    for (int mt = 0; mt < 4; ++mt) {
#pragma unroll
        for (int b = 0; b < 2; ++b) {
            int rr = mt * 16 + qr + 8 * b;
            float cav = ca[rr], cbv = cb[rr];
            float t1 = 0.f, t2 = 0.f;
#pragma unroll
            for (int nt = 0; nt < 8; ++nt) {
                int p0 = wn * 64 + nt * 8 + 2 * qt;
                float h0 = fmaf(cav, acc[mt][nt][2 * b],     fmaf(cbv, suv[p0],     suv[256 + p0]));
                float h1 = fmaf(cav, acc[mt][nt][2 * b + 1], fmaf(cbv, suv[p0 + 1], suv[256 + p0 + 1]));
                acc[mt][nt][2 * b]     = h0;
                acc[mt][nt][2 * b + 1] = h1;
                t1 += h0 + h1;
                t2 += h0 * h0 + h1 * h1;
            }
            t1 += __shfl_xor_sync(0xFFFFFFFFu, t1, 1);
            t2 += __shfl_xor_sync(0xFFFFFFFFu, t2, 1);
            t1 += __shfl_xor_sync(0xFFFFFFFFu, t1, 2);
            t2 += __shfl_xor_sync(0xFFFFFFFFu, t2, 2);
            if (qt == 0) {
                rowacc[(rr * 4 + wn) * 2]     = t1;
                rowacc[(rr * 4 + wn) * 2 + 1] = t2;
            }
        }
    }
    __syncthreads();

    if (tid < 64) {
        float t1 = 0.f, t2 = 0.f;
#pragma unroll
        for (int w = 0; w < 4; ++w) {
            t1 += rowacc[(tid * 4 + w) * 2];
            t2 += rowacc[(tid * 4 + w) * 2 + 1];
        }
        float mu  = t1 * (1.0f / (float)D_PROJ);
        float var = fmaf(-mu, mu, t2 * (1.0f / (float)D_PROJ));
        mu2a[tid] = mu;
        rs2a[tid] = rsqrtf(var + EPS1);
    }
    __syncthreads();

    // ---------------- normalize + store ----------------
    float* outp = out + row0 * D_PROJ;
#pragma unroll
    for (int mt = 0; mt < 4; ++mt) {
#pragma unroll
        for (int b = 0; b < 2; ++b) {
            int rr = mt * 16 + qr + 8 * b;
            float mu = mu2a[rr], rs = rs2a[rr];
#pragma unroll
            for (int nt = 0; nt < 8; ++nt) {
                int p0 = wn * 64 + nt * 8 + 2 * qt;
                float o0 = fmaf((acc[mt][nt][2 * b]     - mu) * rs, suv[512 + p0],     suv[768 + p0]);
                float o1 = fmaf((acc[mt][nt][2 * b + 1] - mu) * rs, suv[512 + p0 + 1], suv[768 + p0 + 1]);
                float2 o = make_float2(o0, o1);
                *(float2*)(outp + (size_t)rr * D_PROJ + p0) = o;
            }
        }
    }
#undef LDA
#undef STATS
#undef STSA
#undef CPB
#undef COMPUTE
#undef ITER
}

// ---------------- launch ----------------
extern "C" void kernel_launch(void* const* d_in, const int* in_sizes, int n_in,
                              void* d_out, int out_size)
{
    const float* x    = (const float*)d_in[0];
    const float* g1   = (const float*)d_in[1];
    const float* b1   = (const float*)d_in[2];
    const float* W    = (const float*)d_in[3];
    const float* bias = (const float*)d_in[4];
    const float* g2   = (const float*)d_in[5];
    const float* b2   = (const float*)d_in[6];
    float* out = (float*)d_out;

    int n_tok = in_sizes[0] / D_MODEL;          // 65536
    int grid  = n_tok / MTILE;                  // 1024

    prep_kernel<<<D_PROJ, 256>>>(W, g1, b1, bias);

    cudaFuncSetAttribute(fused_kernel, cudaFuncAttributeMaxDynamicSharedMemorySize, SMEM_BYTES);
    fused_kernel<<<grid, 128, SMEM_BYTES>>>(x, g2, b2, out);
}

// round 6
// speedup vs baseline: 1.8205x; 1.6902x over previous
#include <cuda_runtime.h>
#include <cstdint>
#include <cstddef>

// ---------------- problem constants ----------------
#define D_MODEL   1024
#define D_PROJ    256
#define MTILE     128                  // rows per CTA
#define NCHUNKS   32                   // K chunks of 32 fp32 (128B per row)
#define EPS1      1e-5f

// smem map (bytes):
//   [0, 4096)      suv: u[256] v[256] g2[256] b2[256]
//   [4096, 6144)   s1p[256] s2p[256]
//   [6144, 7168)   ca[128] cb[128]
//   [8192, ...)    3 stages: A 16KB + B 32KB each
//   epilogue reuses stage0: rowacc[128][4][2] (4KB), mu2[128], rs2[128]
#define SMEM_STAGE_OFF 8192
#define A_BYTES   16384                // 128 rows x 128B
#define B_BYTES   32768                // 256 rows x 128B
#define STAGE_BYTES (A_BYTES + B_BYTES)            // 49152
#define SMEM_BYTES (SMEM_STAGE_OFF + 3 * STAGE_BYTES)   // 155648

// ---------------- device scratch ----------------
// g_Wp layout: [p][kc*32 + s], slot s = 16h+4c+j holds k_local = 16h+c+4j
// (16B logical group G = 4h+c contains k = {16h+c, +4, +8, +12}).
__device__ float g_Wp[D_PROJ * D_MODEL];
__device__ float g_u[D_PROJ];
__device__ float g_v[D_PROJ];

// ---------------- helpers ----------------
static __device__ __forceinline__ uint32_t smem_u32(const void* p) {
    uint32_t a;
    asm("{ .reg .u64 t; cvta.to.shared.u64 t, %1; cvt.u32.u64 %0, t; }" : "=r"(a) : "l"(p));
    return a;
}

// conflict-free group swizzle: sigma(r) = ((r&1)<<2) | ((r>>1)&3)
// - bijective over any 8 consecutive rows (stat reads)
// - rows r, r+1 land in disjoint group halves (fragment lds.128 phases)
// - invariant under row strides 8, 16, 32, 64 (address hoisting)
static __device__ __forceinline__ uint32_t sig(int r) {
    return (((uint32_t)r & 1u) << 2) | (((uint32_t)r >> 1) & 3u);
}

#define CP_COMMIT() asm volatile("cp.async.commit_group;" ::: "memory")
#define CP_WAIT1()  asm volatile("cp.async.wait_group 1;" ::: "memory")

static __device__ __forceinline__ uint32_t f2tf32(float f) {
    uint32_t u;
    asm("cvt.rna.tf32.f32 %0, %1;" : "=r"(u) : "f"(f));
    return u;
}

#define MMA_TF32(d, a0, a1, a2, a3, b0, b1)                                   \
    asm volatile("mma.sync.aligned.m16n8k8.row.col.f32.tf32.tf32.f32 "        \
        "{%0,%1,%2,%3}, {%4,%5,%6,%7}, {%8,%9}, {%0,%1,%2,%3};"               \
        : "+f"((d)[0]), "+f"((d)[1]), "+f"((d)[2]), "+f"((d)[3])              \
        : "r"(a0), "r"(a1), "r"(a2), "r"(a3), "r"(b0), "r"(b1))

#define LDS128F(v, addr)                                                      \
    asm volatile("ld.shared.v4.f32 {%0,%1,%2,%3}, [%4];"                      \
        : "=f"((v).x), "=f"((v).y), "=f"((v).z), "=f"((v).w) : "r"(addr))

#define LDS128U(v, addr)                                                      \
    asm volatile("ld.shared.v4.b32 {%0,%1,%2,%3}, [%4];"                      \
        : "=r"((v).x), "=r"((v).y), "=r"((v).z), "=r"((v).w) : "r"(addr))

// ---------------- prep: W' = g1.*W (tf32-rna), permuted layout; u, v ----------------
__global__ void __launch_bounds__(256) prep_kernel(
    const float* __restrict__ W, const float* __restrict__ g1,
    const float* __restrict__ b1, const float* __restrict__ bias)
{
    __shared__ float ru[8], rv[8];
    int p = blockIdx.x, t = threadIdx.x;
    const float* wrow = W + (size_t)p * D_MODEL;
    float u = 0.f, v = 0.f;
#pragma unroll
    for (int i = 0; i < 4; ++i) {
        int d = t + i * 256;
        float w  = wrow[d];
        float gw = g1[d] * w;
        u += gw;
        v += b1[d] * w;
        int kc = d >> 5, kk = d & 31;
        int h = kk >> 4, c = kk & 3, j = (kk >> 2) & 3;
        int s = (h << 4) | (c << 2) | j;
        g_Wp[(size_t)p * D_MODEL + kc * 32 + s] = __uint_as_float(f2tf32(gw));
    }
#pragma unroll
    for (int o = 16; o > 0; o >>= 1) {
        u += __shfl_xor_sync(0xFFFFFFFFu, u, o);
        v += __shfl_xor_sync(0xFFFFFFFFu, v, o);
    }
    if ((t & 31) == 0) { ru[t >> 5] = u; rv[t >> 5] = v; }
    __syncthreads();
    if (t == 0) {
        float uu = 0.f, vv = 0.f;
#pragma unroll
        for (int i = 0; i < 8; ++i) { uu += ru[i]; vv += rv[i]; }
        g_u[p] = uu;
        g_v[p] = vv + bias[p];
    }
}

// ---------------- main fused kernel ----------------
__global__ void __launch_bounds__(256, 1) fused_kernel(
    const float* __restrict__ x,
    const float* __restrict__ g2v, const float* __restrict__ b2v,
    float* __restrict__ out)
{
    extern __shared__ char smem[];
    const uint32_t sb = smem_u32(smem);
    const int tid  = threadIdx.x;
    const int lane = tid & 31;
    const int wid  = tid >> 5;
    const int wm   = wid >> 2;          // 0..1
    const int wn   = wid & 3;           // 0..3
    const int qt   = lane & 3;
    const int qr   = lane >> 2;

    float* suv = (float*)smem;          // u, v, g2, b2
    suv[tid]       = g_u[tid];
    suv[256 + tid] = g_v[tid];
    suv[512 + tid] = g2v[tid];
    suv[768 + tid] = b2v[tid];

    const size_t row0 = (size_t)blockIdx.x * MTILE;

    // ---- A loader consts: thread covers rows r = 8i + wid, element kk = tid&31 ----
    const int akk = tid & 31;
    const int ahh = akk >> 4, acc_ = akk & 3, ajj = (akk >> 2) & 3;
    const uint32_t aGlog = (uint32_t)(4 * ahh + acc_);
    const uint32_t a_dst = sb + SMEM_STAGE_OFF + (uint32_t)wid * 128
                         + (((aGlog ^ sig(wid)) << 4)) + (uint32_t)ajj * 4;
    const char* a_src = (const char*)x + (row0 + (size_t)wid) * 4096 + (size_t)akk * 4;
    // per i: dst += i*1024, src += i*32768; per chunk: src += kc*128

    // ---- B loader consts: thread covers rows p = 32i + tp, group bq = tid&7 ----
    const int tp = tid >> 3, bq = tid & 7;
    const uint32_t b_dst = sb + SMEM_STAGE_OFF + A_BYTES + (uint32_t)tp * 128
                         + ((((uint32_t)bq ^ sig(tp)) << 4));
    const char* b_src = (const char*)g_Wp + (size_t)tp * 4096 + (size_t)bq * 16;
    // per i: dst += i*4096, src += i*131072; per chunk: src += kc*128

    // ---- fragment bases (sigma invariant under +8/+16/+64 row strides) ----
    const uint32_t qoff = (((uint32_t)qt ^ sig(qr)) << 4);
    const uint32_t aF = sb + SMEM_STAGE_OFF + (uint32_t)(wm * 64 + qr) * 128 + qoff;
    const uint32_t bF = sb + SMEM_STAGE_OFF + A_BYTES + (uint32_t)(wn * 64 + qr) * 128 + qoff;

    // ---- LN1 stat consts: thread -> (row srow, half shh) ----
    const int srow = tid & 127, shh = tid >> 7;
    const uint32_t sBase = sb + SMEM_STAGE_OFF + (uint32_t)srow * 128;
    const uint32_t ssig = sig(srow);
    uint32_t sOff[4];
#pragma unroll
    for (int i = 0; i < 4; ++i)
        sOff[i] = (((uint32_t)(shh * 4 + i) ^ ssig) << 4);

    float acc[4][8][4];
#pragma unroll
    for (int a = 0; a < 4; ++a)
#pragma unroll
        for (int b = 0; b < 8; ++b)
#pragma unroll
            for (int c = 0; c < 4; ++c) acc[a][b][c] = 0.f;

    float s1 = 0.f, s2 = 0.f;

#define LOADC(KC, SOFF)                                                        \
    do {                                                                       \
        const char* _a = a_src + (size_t)(KC) * 128;                           \
        _Pragma("unroll")                                                      \
        for (int i = 0; i < 16; ++i)                                           \
            asm volatile("cp.async.ca.shared.global [%0], [%1], 4;"            \
                :: "r"(a_dst + (SOFF) + (uint32_t)i * 1024),                   \
                   "l"(_a + (size_t)i * 32768));                               \
        const char* _b = b_src + (size_t)(KC) * 128;                           \
        _Pragma("unroll")                                                      \
        for (int i = 0; i < 8; ++i)                                            \
            asm volatile("cp.async.cg.shared.global [%0], [%1], 16;"           \
                :: "r"(b_dst + (SOFF) + (uint32_t)i * 4096),                   \
                   "l"(_b + (size_t)i * 131072));                              \
    } while (0)

#define STATS(SOFF)                                                            \
    do {                                                                       \
        _Pragma("unroll")                                                      \
        for (int i = 0; i < 4; ++i) {                                          \
            float4 vv;                                                         \
            LDS128F(vv, sBase + (SOFF) + sOff[i]);                             \
            s1 += (vv.x + vv.y) + (vv.z + vv.w);                               \
            s2 += (vv.x * vv.x + vv.y * vv.y) + (vv.z * vv.z + vv.w * vv.w);   \
        }                                                                      \
    } while (0)

#define COMPUTE(SOFF)                                                          \
    do {                                                                       \
        _Pragma("unroll")                                                      \
        for (int h = 0; h < 2; ++h) {                                          \
            const uint32_t _af = (aF + (SOFF)) ^ ((uint32_t)h << 6);           \
            const uint32_t _bf = (bF + (SOFF)) ^ ((uint32_t)h << 6);           \
            uint4 bb[8];                                                       \
            _Pragma("unroll")                                                  \
            for (int nt = 0; nt < 8; ++nt)                                     \
                LDS128U(bb[nt], _bf + (uint32_t)nt * 1024);                    \
            _Pragma("unroll")                                                  \
            for (int mt = 0; mt < 4; ++mt) {                                   \
                float4 alo, ahi;                                               \
                LDS128F(alo, _af + (uint32_t)mt * 2048);                       \
                LDS128F(ahi, _af + (uint32_t)mt * 2048 + 1024);                \
                uint32_t a0s0 = f2tf32(alo.x), a1s0 = f2tf32(ahi.x);           \
                uint32_t a2s0 = f2tf32(alo.y), a3s0 = f2tf32(ahi.y);           \
                uint32_t a0s1 = f2tf32(alo.z), a1s1 = f2tf32(ahi.z);           \
                uint32_t a2s1 = f2tf32(alo.w), a3s1 = f2tf32(ahi.w);           \
                _Pragma("unroll")                                              \
                for (int nt = 0; nt < 8; ++nt) {                               \
                    MMA_TF32(acc[mt][nt], a0s0, a1s0, a2s0, a3s0,              \
                             bb[nt].x, bb[nt].y);                              \
                    MMA_TF32(acc[mt][nt], a0s1, a1s1, a2s1, a3s1,              \
                             bb[nt].z, bb[nt].w);                              \
                }                                                              \
            }                                                                  \
        }                                                                      \
    } while (0)

    // ---------------- mainloop: 3-stage pipeline, wait_group 1 ----------------
    LOADC(0, 0u); CP_COMMIT();
    LOADC(1, (uint32_t)STAGE_BYTES); CP_COMMIT();

    uint32_t soff = 0;
#pragma unroll 1
    for (int kc = 0; kc < NCHUNKS; ++kc) {
        CP_WAIT1();                     // chunk kc resident
        __syncthreads();                // stage (kc+2)%3 free for overwrite
        if (kc + 2 < NCHUNKS) {
            uint32_t so2 = (soff == 0) ? 2u * STAGE_BYTES : soff - STAGE_BYTES;
            LOADC(kc + 2, so2);
        }
        CP_COMMIT();
        STATS(soff);
        COMPUTE(soff);
        soff = (soff == 2u * STAGE_BYTES) ? 0u : soff + STAGE_BYTES;
    }

    // ---------------- LN1 finalize ----------------
    float* s1p = (float*)(smem + 4096);
    float* s2p = s1p + 256;
    float* ca = (float*)(smem + 6144);
    float* cb = ca + 128;
    float* rowacc = (float*)(smem + SMEM_STAGE_OFF);        // [128][4][2]
    float* mu2a = (float*)(smem + SMEM_STAGE_OFF + 4096);
    float* rs2a = mu2a + 128;

    s1p[tid] = s1; s2p[tid] = s2;
    __syncthreads();

    if (tid < 128) {
        float a = s1p[tid] + s1p[tid + 128];
        float b = s2p[tid] + s2p[tid + 128];
        float mu  = a * (1.0f / (float)D_MODEL);
        float var = fmaf(-mu, mu, b * (1.0f / (float)D_MODEL));
        float rs  = rsqrtf(var + EPS1);
        ca[tid] = rs;
        cb[tid] = -mu * rs;
    }
    rowacc[tid] = 0.f; rowacc[tid + 256] = 0.f;
    rowacc[tid + 512] = 0.f; rowacc[tid + 768] = 0.f;
    __syncthreads();

    // ---------------- h = ca*acc + cb*u + v; LN2 partial sums ----------------
#pragma unroll
    for (int mt = 0; mt < 4; ++mt) {
#pragma unroll
        for (int b = 0; b < 2; ++b) {
            int rr = wm * 64 + mt * 16 + qr + 8 * b;
            float cav = ca[rr], cbv = cb[rr];
            float t1 = 0.f, t2 = 0.f;
#pragma unroll
            for (int nt = 0; nt < 8; ++nt) {
                int p0 = wn * 64 + nt * 8 + 2 * qt;
                float h0 = fmaf(cav, acc[mt][nt][2 * b],     fmaf(cbv, suv[p0],     suv[256 + p0]));
                float h1 = fmaf(cav, acc[mt][nt][2 * b + 1], fmaf(cbv, suv[p0 + 1], suv[256 + p0 + 1]));
                acc[mt][nt][2 * b]     = h0;
                acc[mt][nt][2 * b + 1] = h1;
                t1 += h0 + h1;
                t2 += h0 * h0 + h1 * h1;
            }
            t1 += __shfl_xor_sync(0xFFFFFFFFu, t1, 1);
            t2 += __shfl_xor_sync(0xFFFFFFFFu, t2, 1);
            t1 += __shfl_xor_sync(0xFFFFFFFFu, t1, 2);
            t2 += __shfl_xor_sync(0xFFFFFFFFu, t2, 2);
            if (qt == 0) {
                rowacc[(rr * 4 + wn) * 2]     = t1;
                rowacc[(rr * 4 + wn) * 2 + 1] = t2;
            }
        }
    }
    __syncthreads();

    if (tid < 128) {
        float t1 = 0.f, t2 = 0.f;
#pragma unroll
        for (int w = 0; w < 4; ++w) {
            t1 += rowacc[(tid * 4 + w) * 2];
            t2 += rowacc[(tid * 4 + w) * 2 + 1];
        }
        float mu  = t1 * (1.0f / (float)D_PROJ);
        float var = fmaf(-mu, mu, t2 * (1.0f / (float)D_PROJ));
        mu2a[tid] = mu;
        rs2a[tid] = rsqrtf(var + EPS1);
    }
    __syncthreads();

    // ---------------- normalize + store ----------------
    float* outp = out + row0 * D_PROJ;
#pragma unroll
    for (int mt = 0; mt < 4; ++mt) {
#pragma unroll
        for (int b = 0; b < 2; ++b) {
            int rr = wm * 64 + mt * 16 + qr + 8 * b;
            float mu = mu2a[rr], rs = rs2a[rr];
#pragma unroll
            for (int nt = 0; nt < 8; ++nt) {
                int p0 = wn * 64 + nt * 8 + 2 * qt;
                float o0 = fmaf((acc[mt][nt][2 * b]     - mu) * rs, suv[512 + p0],     suv[768 + p0]);
                float o1 = fmaf((acc[mt][nt][2 * b + 1] - mu) * rs, suv[512 + p0 + 1], suv[768 + p0 + 1]);
                float2 o = make_float2(o0, o1);
                *(float2*)(outp + (size_t)rr * D_PROJ + p0) = o;
            }
        }
    }
#undef LOADC
#undef STATS
#undef COMPUTE
}

// ---------------- launch ----------------
extern "C" void kernel_launch(void* const* d_in, const int* in_sizes, int n_in,
                              void* d_out, int out_size)
{
    const float* x    = (const float*)d_in[0];
    const float* g1   = (const float*)d_in[1];
    const float* b1   = (const float*)d_in[2];
    const float* W    = (const float*)d_in[3];
    const float* bias = (const float*)d_in[4];
    const float* g2   = (const float*)d_in[5];
    const float* b2   = (const float*)d_in[6];
    float* out = (float*)d_out;

    int n_tok = in_sizes[0] / D_MODEL;          // 65536
    int grid  = n_tok / MTILE;                  // 512

    prep_kernel<<<D_PROJ, 256>>>(W, g1, b1, bias);

    cudaFuncSetAttribute(fused_kernel, cudaFuncAttributeMaxDynamicSharedMemorySize, SMEM_BYTES);
    fused_kernel<<<grid, 256, SMEM_BYTES>>>(x, g2, b2, out);
}

// round 7
// speedup vs baseline: 1.9757x; 1.0853x over previous
#include <cuda_runtime.h>
#include <cstdint>
#include <cstddef>

// ---------------- problem constants ----------------
#define D_MODEL   1024
#define D_PROJ    256
#define MTILE     128                  // rows per CTA
#define NCHUNKS   32                   // K chunks of 32 fp32 (128B per row)
#define EPS1      1e-5f

// smem map (bytes):
//   [0, 4096)      suv: u[256] v[256] g2[256] b2[256]
//   [4096, 6144)   s1p[256] s2p[256]
//   [6144, 7168)   ca[128] cb[128]
//   [8192, ...)    3 stages: A 16KB + B 32KB each
//   epilogue reuses stage0: rowacc[128][4][2] (4KB), mu2[128], rs2[128]
#define SMEM_STAGE_OFF 8192
#define A_BYTES   16384                // 128 rows x 128B
#define B_BYTES   32768                // 256 rows x 128B
#define STAGE_BYTES (A_BYTES + B_BYTES)            // 49152
#define SMEM_BYTES (SMEM_STAGE_OFF + 3 * STAGE_BYTES)   // 155648

// ---------------- device scratch ----------------
// g_Wp layout: [p][kc*32 + s], slot s = 16h+4c+j holds k_local = 16h+c+4j
// (16B logical group G = 4h+c contains k = {16h+c, +4, +8, +12}).
__device__ float g_Wp[D_PROJ * D_MODEL];
__device__ float g_u[D_PROJ];
__device__ float g_v[D_PROJ];

// ---------------- helpers ----------------
static __device__ __forceinline__ uint32_t smem_u32(const void* p) {
    uint32_t a;
    asm("{ .reg .u64 t; cvta.to.shared.u64 t, %1; cvt.u32.u64 %0, t; }" : "=r"(a) : "l"(p));
    return a;
}

// conflict-free group swizzle: sigma(r) = ((r&1)<<2) | ((r>>1)&3)
static __device__ __forceinline__ uint32_t sig(int r) {
    return (((uint32_t)r & 1u) << 2) | (((uint32_t)r >> 1) & 3u);
}

#define CP_COMMIT() asm volatile("cp.async.commit_group;" ::: "memory")
#define CP_WAIT1()  asm volatile("cp.async.wait_group 1;" ::: "memory")

static __device__ __forceinline__ uint32_t f2tf32(float f) {
    uint32_t u;
    asm("cvt.rna.tf32.f32 %0, %1;" : "=r"(u) : "f"(f));
    return u;
}

// raw fp32 bits fed to tf32 MMA: HW uses the tf32 bit positions (truncation round)
#define MMA_TF32(d, a0, a1, a2, a3, b0, b1)                                   \
    asm volatile("mma.sync.aligned.m16n8k8.row.col.f32.tf32.tf32.f32 "        \
        "{%0,%1,%2,%3}, {%4,%5,%6,%7}, {%8,%9}, {%0,%1,%2,%3};"               \
        : "+f"((d)[0]), "+f"((d)[1]), "+f"((d)[2]), "+f"((d)[3])              \
        : "r"(a0), "r"(a1), "r"(a2), "r"(a3), "r"(b0), "r"(b1))

#define LDS128F(v, addr)                                                      \
    asm volatile("ld.shared.v4.f32 {%0,%1,%2,%3}, [%4];"                      \
        : "=f"((v).x), "=f"((v).y), "=f"((v).z), "=f"((v).w) : "r"(addr))

#define LDS128U(v, addr)                                                      \
    asm volatile("ld.shared.v4.b32 {%0,%1,%2,%3}, [%4];"                      \
        : "=r"((v).x), "=r"((v).y), "=r"((v).z), "=r"((v).w) : "r"(addr))

// ---------------- prep: W' = g1.*W (tf32-rna), permuted layout; u, v ----------------
__global__ void __launch_bounds__(256) prep_kernel(
    const float* __restrict__ W, const float* __restrict__ g1,
    const float* __restrict__ b1, const float* __restrict__ bias)
{
    __shared__ float ru[8], rv[8];
    int p = blockIdx.x, t = threadIdx.x;
    const float* wrow = W + (size_t)p * D_MODEL;
    float u = 0.f, v = 0.f;
#pragma unroll
    for (int i = 0; i < 4; ++i) {
        int d = t + i * 256;
        float w  = wrow[d];
        float gw = g1[d] * w;
        u += gw;
        v += b1[d] * w;
        int kc = d >> 5, kk = d & 31;
        int h = kk >> 4, c = kk & 3, j = (kk >> 2) & 3;
        int s = (h << 4) | (c << 2) | j;
        g_Wp[(size_t)p * D_MODEL + kc * 32 + s] = __uint_as_float(f2tf32(gw));
    }
#pragma unroll
    for (int o = 16; o > 0; o >>= 1) {
        u += __shfl_xor_sync(0xFFFFFFFFu, u, o);
        v += __shfl_xor_sync(0xFFFFFFFFu, v, o);
    }
    if ((t & 31) == 0) { ru[t >> 5] = u; rv[t >> 5] = v; }
    __syncthreads();
    if (t == 0) {
        float uu = 0.f, vv = 0.f;
#pragma unroll
        for (int i = 0; i < 8; ++i) { uu += ru[i]; vv += rv[i]; }
        g_u[p] = uu;
        g_v[p] = vv + bias[p];
    }
}

// ---------------- main fused kernel ----------------
__global__ void __launch_bounds__(256, 1) fused_kernel(
    const float* __restrict__ x,
    const float* __restrict__ g2v, const float* __restrict__ b2v,
    float* __restrict__ out)
{
    extern __shared__ char smem[];
    const uint32_t sb = smem_u32(smem);
    const int tid  = threadIdx.x;
    const int lane = tid & 31;
    const int wid  = tid >> 5;
    const int wm   = wid >> 2;          // 0..1
    const int wn   = wid & 3;           // 0..3
    const int qt   = lane & 3;
    const int qr   = lane >> 2;

    float* suv = (float*)smem;          // u, v, g2, b2
    suv[tid]       = g_u[tid];
    suv[256 + tid] = g_v[tid];
    suv[512 + tid] = g2v[tid];
    suv[768 + tid] = b2v[tid];

    const size_t row0 = (size_t)blockIdx.x * MTILE;

    // ---- A loader consts: thread covers rows r = 8i + wid, element kk = tid&31 ----
    const int akk = tid & 31;
    const int ahh = akk >> 4, acc_ = akk & 3, ajj = (akk >> 2) & 3;
    const uint32_t aGlog = (uint32_t)(4 * ahh + acc_);
    const uint32_t a_dst = sb + SMEM_STAGE_OFF + (uint32_t)wid * 128
                         + (((aGlog ^ sig(wid)) << 4)) + (uint32_t)ajj * 4;
    const char* a_src = (const char*)x + (row0 + (size_t)wid) * 4096 + (size_t)akk * 4;

    // ---- B loader consts: thread covers rows p = 32i + tp, group bq = tid&7 ----
    const int tp = tid >> 3, bq = tid & 7;
    const uint32_t b_dst = sb + SMEM_STAGE_OFF + A_BYTES + (uint32_t)tp * 128
                         + ((((uint32_t)bq ^ sig(tp)) << 4));
    const char* b_src = (const char*)g_Wp + (size_t)tp * 4096 + (size_t)bq * 16;

    // ---- fragment bases, both halves precomputed (h enters via XOR 64) ----
    const uint32_t qoff = (((uint32_t)qt ^ sig(qr)) << 4);
    const uint32_t aRow = sb + SMEM_STAGE_OFF + (uint32_t)(wm * 64 + qr) * 128;
    const uint32_t bRow = sb + SMEM_STAGE_OFF + A_BYTES + (uint32_t)(wn * 64 + qr) * 128;
    const uint32_t aF0 = aRow + qoff;
    const uint32_t aF1 = aRow + (qoff ^ 64u);
    const uint32_t bF0 = bRow + qoff;
    const uint32_t bF1 = bRow + (qoff ^ 64u);

    // ---- LN1 stat consts ----
    const int srow = tid & 127, shh = tid >> 7;
    const uint32_t sBase = sb + SMEM_STAGE_OFF + (uint32_t)srow * 128;
    const uint32_t ssig = sig(srow);
    uint32_t sOff[4];
#pragma unroll
    for (int i = 0; i < 4; ++i)
        sOff[i] = (((uint32_t)(shh * 4 + i) ^ ssig) << 4);

    float acc[4][8][4];
#pragma unroll
    for (int a = 0; a < 4; ++a)
#pragma unroll
        for (int b = 0; b < 8; ++b)
#pragma unroll
            for (int c = 0; c < 4; ++c) acc[a][b][c] = 0.f;

    float s1 = 0.f, s2 = 0.f;

#define LOADC(KC, SOFF)                                                        \
    do {                                                                       \
        const char* _a = a_src + (size_t)(KC) * 128;                           \
        _Pragma("unroll")                                                      \
        for (int i = 0; i < 16; ++i)                                           \
            asm volatile("cp.async.ca.shared.global [%0], [%1], 4;"            \
                :: "r"(a_dst + (SOFF) + (uint32_t)i * 1024),                   \
                   "l"(_a + (size_t)i * 32768));                               \
        const char* _b = b_src + (size_t)(KC) * 128;                           \
        _Pragma("unroll")                                                      \
        for (int i = 0; i < 8; ++i)                                            \
            asm volatile("cp.async.cg.shared.global [%0], [%1], 16;"           \
                :: "r"(b_dst + (SOFF) + (uint32_t)i * 4096),                   \
                   "l"(_b + (size_t)i * 131072));                              \
    } while (0)

#define STATS(SOFF)                                                            \
    do {                                                                       \
        _Pragma("unroll")                                                      \
        for (int i = 0; i < 4; ++i) {                                          \
            float4 vv;                                                         \
            LDS128F(vv, sBase + (SOFF) + sOff[i]);                             \
            s1 += (vv.x + vv.y) + (vv.z + vv.w);                               \
            s2 += (vv.x * vv.x + vv.y * vv.y) + (vv.z * vv.z + vv.w * vv.w);   \
        }                                                                      \
    } while (0)

// raw fp32 bits straight into the tf32 MMA — no cvt in the hot loop
#define COMPUTE(SOFF)                                                          \
    do {                                                                       \
        _Pragma("unroll")                                                      \
        for (int h = 0; h < 2; ++h) {                                          \
            const uint32_t _af = (h ? aF1 : aF0) + (SOFF);                     \
            const uint32_t _bf = (h ? bF1 : bF0) + (SOFF);                     \
            uint4 bb[8];                                                       \
            _Pragma("unroll")                                                  \
            for (int nt = 0; nt < 8; ++nt)                                     \
                LDS128U(bb[nt], _bf + (uint32_t)nt * 1024);                    \
            _Pragma("unroll")                                                  \
            for (int mt = 0; mt < 4; ++mt) {                                   \
                uint4 alo, ahi;                                                \
                LDS128U(alo, _af + (uint32_t)mt * 2048);                       \
                LDS128U(ahi, _af + (uint32_t)mt * 2048 + 1024);                \
                _Pragma("unroll")                                              \
                for (int nt = 0; nt < 8; ++nt) {                               \
                    MMA_TF32(acc[mt][nt], alo.x, ahi.x, alo.y, ahi.y,          \
                             bb[nt].x, bb[nt].y);                              \
                    MMA_TF32(acc[mt][nt], alo.z, ahi.z, alo.w, ahi.w,          \
                             bb[nt].z, bb[nt].w);                              \
                }                                                              \
            }                                                                  \
        }                                                                      \
    } while (0)

    // ---------------- mainloop: 3-stage pipeline, wait_group 1 ----------------
    LOADC(0, 0u); CP_COMMIT();
    LOADC(1, (uint32_t)STAGE_BYTES); CP_COMMIT();

    uint32_t soff = 0;
#pragma unroll 1
    for (int kc = 0; kc < NCHUNKS; ++kc) {
        CP_WAIT1();                     // chunk kc resident
        __syncthreads();                // stage (kc+2)%3 free for overwrite
        if (kc + 2 < NCHUNKS) {
            uint32_t so2 = (soff == 0) ? 2u * STAGE_BYTES : soff - STAGE_BYTES;
            LOADC(kc + 2, so2);
        }
        CP_COMMIT();
        STATS(soff);
        COMPUTE(soff);
        soff = (soff == 2u * STAGE_BYTES) ? 0u : soff + STAGE_BYTES;
    }

    // ---------------- LN1 finalize ----------------
    float* s1p = (float*)(smem + 4096);
    float* s2p = s1p + 256;
    float* ca = (float*)(smem + 6144);
    float* cb = ca + 128;
    float* rowacc = (float*)(smem + SMEM_STAGE_OFF);        // [128][4][2]
    float* mu2a = (float*)(smem + SMEM_STAGE_OFF + 4096);
    float* rs2a = mu2a + 128;

    s1p[tid] = s1; s2p[tid] = s2;
    __syncthreads();

    if (tid < 128) {
        float a = s1p[tid] + s1p[tid + 128];
        float b = s2p[tid] + s2p[tid + 128];
        float mu  = a * (1.0f / (float)D_MODEL);
        float var = fmaf(-mu, mu, b * (1.0f / (float)D_MODEL));
        float rs  = rsqrtf(var + EPS1);
        ca[tid] = rs;
        cb[tid] = -mu * rs;
    }
    rowacc[tid] = 0.f; rowacc[tid + 256] = 0.f;
    rowacc[tid + 512] = 0.f; rowacc[tid + 768] = 0.f;
    __syncthreads();

    // ---------------- h = ca*acc + cb*u + v; LN2 partial sums ----------------
#pragma unroll
    for (int mt = 0; mt < 4; ++mt) {
#pragma unroll
        for (int b = 0; b < 2; ++b) {
            int rr = wm * 64 + mt * 16 + qr + 8 * b;
            float cav = ca[rr], cbv = cb[rr];
            float t1 = 0.f, t2 = 0.f;
#pragma unroll
            for (int nt = 0; nt < 8; ++nt) {
                int p0 = wn * 64 + nt * 8 + 2 * qt;
                float h0 = fmaf(cav, acc[mt][nt][2 * b],     fmaf(cbv, suv[p0],     suv[256 + p0]));
                float h1 = fmaf(cav, acc[mt][nt][2 * b + 1], fmaf(cbv, suv[p0 + 1], suv[256 + p0 + 1]));
                acc[mt][nt][2 * b]     = h0;
                acc[mt][nt][2 * b + 1] = h1;
                t1 += h0 + h1;
                t2 += h0 * h0 + h1 * h1;
            }
            t1 += __shfl_xor_sync(0xFFFFFFFFu, t1, 1);
            t2 += __shfl_xor_sync(0xFFFFFFFFu, t2, 1);
            t1 += __shfl_xor_sync(0xFFFFFFFFu, t1, 2);
            t2 += __shfl_xor_sync(0xFFFFFFFFu, t2, 2);
            if (qt == 0) {
                rowacc[(rr * 4 + wn) * 2]     = t1;
                rowacc[(rr * 4 + wn) * 2 + 1] = t2;
            }
        }
    }
    __syncthreads();

    if (tid < 128) {
        float t1 = 0.f, t2 = 0.f;
#pragma unroll
        for (int w = 0; w < 4; ++w) {
            t1 += rowacc[(tid * 4 + w) * 2];
            t2 += rowacc[(tid * 4 + w) * 2 + 1];
        }
        float mu  = t1 * (1.0f / (float)D_PROJ);
        float var = fmaf(-mu, mu, t2 * (1.0f / (float)D_PROJ));
        mu2a[tid] = mu;
        rs2a[tid] = rsqrtf(var + EPS1);
    }
    __syncthreads();

    // ---------------- normalize + store ----------------
    float* outp = out + row0 * D_PROJ;
#pragma unroll
    for (int mt = 0; mt < 4; ++mt) {
#pragma unroll
        for (int b = 0; b < 2; ++b) {
            int rr = wm * 64 + mt * 16 + qr + 8 * b;
            float mu = mu2a[rr], rs = rs2a[rr];
#pragma unroll
            for (int nt = 0; nt < 8; ++nt) {
                int p0 = wn * 64 + nt * 8 + 2 * qt;
                float o0 = fmaf((acc[mt][nt][2 * b]     - mu) * rs, suv[512 + p0],     suv[768 + p0]);
                float o1 = fmaf((acc[mt][nt][2 * b + 1] - mu) * rs, suv[512 + p0 + 1], suv[768 + p0 + 1]);
                float2 o = make_float2(o0, o1);
                *(float2*)(outp + (size_t)rr * D_PROJ + p0) = o;
            }
        }
    }
#undef LOADC
#undef STATS
#undef COMPUTE
}

// ---------------- launch ----------------
extern "C" void kernel_launch(void* const* d_in, const int* in_sizes, int n_in,
                              void* d_out, int out_size)
{
    const float* x    = (const float*)d_in[0];
    const float* g1   = (const float*)d_in[1];
    const float* b1   = (const float*)d_in[2];
    const float* W    = (const float*)d_in[3];
    const float* bias = (const float*)d_in[4];
    const float* g2   = (const float*)d_in[5];
    const float* b2   = (const float*)d_in[6];
    float* out = (float*)d_out;

    int n_tok = in_sizes[0] / D_MODEL;          // 65536
    int grid  = n_tok / MTILE;                  // 512

    prep_kernel<<<D_PROJ, 256>>>(W, g1, b1, bias);

    cudaFuncSetAttribute(fused_kernel, cudaFuncAttributeMaxDynamicSharedMemorySize, SMEM_BYTES);
    fused_kernel<<<grid, 256, SMEM_BYTES>>>(x, g2, b2, out);
}